// round 2
// baseline (speedup 1.0000x reference)
#include <cuda_runtime.h>
#include <math.h>

#define BATCH 8
#define SEQ   1024
#define CH    768
#define NH    12
#define HD    64
#define BH    (BATCH*NH)   /* 96 */

// ---- scratch (allocation-free rule: __device__ globals) ----
__device__ float g_qkv[(size_t)BATCH*SEQ*3*CH];     // 18.9M  (also reused as AV output)
__device__ float g_q  [(size_t)BH*SEQ*HD];          // 6.29M
__device__ float g_kT [(size_t)BH*HD*SEQ];          // 6.29M  (pre-transposed K)
__device__ float g_v  [(size_t)BH*SEQ*HD];          // 6.29M
__device__ float g_scores[(size_t)BH*SEQ*SEQ];      // 100.7M (402MB)
__device__ float g_heads[(size_t)BATCH*SEQ*CH];     // 6.29M

// ============================================================
// Generic batched row-major SGEMM: C = alpha * A@B (+ bias[col])
// All problem dims here are exact multiples of tiles -> no guards.
// ============================================================
template<int BM,int BN,int BK,int TM,int TN>
__global__ void sgemm(int K,
                      const float* __restrict__ A, int lda, long long sA,
                      const float* __restrict__ B, int ldb, long long sB,
                      float*       __restrict__ C, int ldc, long long sC,
                      float alpha, const float* __restrict__ bias)
{
    constexpr int THREADS = (BM/TM)*(BN/TN);
    __shared__ float As[BK][BM];
    __shared__ float Bs[BK][BN];

    const int tid = threadIdx.x;
    const long long bz = blockIdx.z;
    A += bz*sA + (long long)blockIdx.y*BM*lda;
    B += bz*sB + (long long)blockIdx.x*BN;
    C += bz*sC + (long long)blockIdx.y*BM*ldc + (long long)blockIdx.x*BN;
    const float* biasp = bias ? (bias + (long long)blockIdx.x*BN) : nullptr;

    const int tcol = tid % (BN/TN);
    const int trow = tid / (BN/TN);

    float acc[TM][TN];
    #pragma unroll
    for (int i=0;i<TM;i++)
        #pragma unroll
        for (int j=0;j<TN;j++) acc[i][j]=0.f;

    constexpr int A_F4 = BM*BK/4;
    constexpr int B_F4 = BK*BN/4;
    constexpr int A_PER = (A_F4 + THREADS-1)/THREADS;
    constexpr int B_PER = (B_F4 + THREADS-1)/THREADS;

    for (int k0 = 0; k0 < K; k0 += BK) {
        #pragma unroll
        for (int t = 0; t < A_PER; t++) {
            int i = tid + t*THREADS;
            if ((A_F4 % THREADS == 0) || (i < A_F4)) {
                int row = i / (BK/4);
                int c4  = i % (BK/4);
                float4 v4 = *(const float4*)&A[(long long)row*lda + k0 + c4*4];
                As[c4*4+0][row] = v4.x;
                As[c4*4+1][row] = v4.y;
                As[c4*4+2][row] = v4.z;
                As[c4*4+3][row] = v4.w;
            }
        }
        #pragma unroll
        for (int t = 0; t < B_PER; t++) {
            int i = tid + t*THREADS;
            if ((B_F4 % THREADS == 0) || (i < B_F4)) {
                int row = i / (BN/4);
                int c4  = i % (BN/4);
                float4 v4 = *(const float4*)&B[(long long)(k0+row)*ldb + c4*4];
                *(float4*)&Bs[row][c4*4] = v4;
            }
        }
        __syncthreads();

        #pragma unroll
        for (int k = 0; k < BK; k++) {
            float ar[TM], br[TN];
            #pragma unroll
            for (int i=0;i<TM;i++) ar[i] = As[k][trow*TM+i];
            #pragma unroll
            for (int j=0;j<TN;j++) br[j] = Bs[k][tcol*TN+j];
            #pragma unroll
            for (int i=0;i<TM;i++)
                #pragma unroll
                for (int j=0;j<TN;j++)
                    acc[i][j] += ar[i]*br[j];
        }
        __syncthreads();
    }

    #pragma unroll
    for (int i=0;i<TM;i++) {
        long long row = (long long)(trow*TM+i)*ldc;
        #pragma unroll
        for (int j=0;j<TN;j++) {
            int col = tcol*TN+j;
            float v = alpha*acc[i][j];
            if (biasp) v += biasp[col];
            C[row + col] = v;
        }
    }
}

// split qkv [B,N,3C] -> q [BH,N,D], kT [BH,D,N], v [BH,N,D]
__global__ void reorder_qkv()
{
    long long idx = (long long)blockIdx.x*blockDim.x + threadIdx.x;
    const long long total = (long long)BATCH*SEQ*3*CH;
    if (idx >= total) return;
    int c = (int)(idx % (3*CH));
    long long r = idx / (3*CH);
    int n = (int)(r % SEQ);
    int b = (int)(r / SEQ);
    int which = c / CH;
    int hc = c % CH;
    int h = hc / HD;
    int d = hc % HD;
    float val = g_qkv[idx];
    long long bh = (long long)b*NH + h;
    if (which == 0)      g_q [(bh*SEQ + n)*HD + d] = val;
    else if (which == 1) g_kT[(bh*HD  + d)*SEQ + n] = val;
    else                 g_v [(bh*SEQ + n)*HD + d] = val;
}

// src [B,H,N,D] -> g_heads [B,N,H*D]
__global__ void reorder_heads(const float* __restrict__ src)
{
    long long idx = (long long)blockIdx.x*blockDim.x + threadIdx.x;
    const long long total = (long long)BATCH*SEQ*CH;
    if (idx >= total) return;
    int c = (int)(idx % CH);
    long long r = idx / CH;
    int n = (int)(r % SEQ);
    int b = (int)(r / SEQ);
    int h = c / HD;
    int d = c % HD;
    g_heads[idx] = src[(((long long)b*NH + h)*SEQ + n)*HD + d];
}

__inline__ __device__ float warpReduceMax(float v){
    #pragma unroll
    for (int o=16;o;o>>=1) v = fmaxf(v, __shfl_xor_sync(0xffffffffu, v, o));
    return v;
}
__inline__ __device__ float warpReduceSum(float v){
    #pragma unroll
    for (int o=16;o;o>>=1) v += __shfl_xor_sync(0xffffffffu, v, o);
    return v;
}

// one block (256 threads) per row of 1024
__global__ void softmax_rows(const float* __restrict__ src, float* __restrict__ dst)
{
    long long row = blockIdx.x;
    const float* p = src + row*SEQ;
    float*       o = dst + row*SEQ;
    int t = threadIdx.x;
    __shared__ float sred[8];

    float v[4];
    float m = -1e30f;
    #pragma unroll
    for (int j=0;j<4;j++){ v[j] = p[t + j*256]; m = fmaxf(m, v[j]); }

    m = warpReduceMax(m);
    if ((t & 31) == 0) sred[t>>5] = m;
    __syncthreads();
    if (t < 32) {
        float x = (t < 8) ? sred[t] : -1e30f;
        x = warpReduceMax(x);
        if (t == 0) sred[0] = x;
    }
    __syncthreads();
    m = sred[0];
    __syncthreads();

    float s = 0.f;
    #pragma unroll
    for (int j=0;j<4;j++){ v[j] = expf(v[j]-m); s += v[j]; }
    s = warpReduceSum(s);
    if ((t & 31) == 0) sred[t>>5] = s;
    __syncthreads();
    if (t < 32) {
        float x = (t < 8) ? sred[t] : 0.f;
        x = warpReduceSum(x);
        if (t == 0) sred[0] = x;
    }
    __syncthreads();
    float inv = 1.0f / sred[0];
    #pragma unroll
    for (int j=0;j<4;j++) o[t + j*256] = v[j]*inv;
}

extern "C" void kernel_launch(void* const* d_in, const int* in_sizes, int n_in,
                              void* d_out, int out_size)
{
    const float* x      = (const float*)d_in[0];   // [8,1024,768]
    const float* w_qkv  = (const float*)d_in[1];   // [768,2304]
    const float* w_proj = (const float*)d_in[2];   // [768,768]
    const float* b_proj = (const float*)d_in[3];   // [768]
    float* out = (float*)d_out;

    float *qkv, *q, *kT, *v, *scores, *heads;
    cudaGetSymbolAddress((void**)&qkv,    g_qkv);
    cudaGetSymbolAddress((void**)&q,      g_q);
    cudaGetSymbolAddress((void**)&kT,     g_kT);
    cudaGetSymbolAddress((void**)&v,      g_v);
    cudaGetSymbolAddress((void**)&scores, g_scores);
    cudaGetSymbolAddress((void**)&heads,  g_heads);

    const long long OUTE  = (long long)BATCH*SEQ*CH;        // 6,291,456
    const long long ATTNE = (long long)BH*SEQ*SEQ;          // 100,663,296
    // attn is the second tuple output; fall back to scratch if d_out is out-only
    float* attn_dst = ((long long)out_size >= OUTE + ATTNE) ? (out + OUTE) : scores;

    // 1. qkv = x @ w_qkv            [8192,768] x [768,2304]
    sgemm<128,128,8,8,8><<<dim3(3*CH/128, (BATCH*SEQ)/128, 1), 256>>>(
        CH, x, CH, 0, w_qkv, 3*CH, 0, qkv, 3*CH, 0, 1.0f, nullptr);

    // 2. split into q / kT / v
    {
        long long total = (long long)BATCH*SEQ*3*CH;
        reorder_qkv<<<(unsigned)((total + 255)/256), 256>>>();
    }

    // 3. scores = (1/8) * q @ kT    batched [1024,64] x [64,1024], 96 batches
    sgemm<128,128,8,8,8><<<dim3(SEQ/128, SEQ/128, BH), 256>>>(
        HD, q, HD, (long long)SEQ*HD,
        kT, SEQ, (long long)HD*SEQ,
        scores, SEQ, (long long)SEQ*SEQ,
        0.125f, nullptr);

    // 4. softmax rows -> attn output region (also the AV input)
    softmax_rows<<<BH*SEQ, 256>>>(scores, attn_dst);

    // 5. av = attn @ v              batched [1024,1024] x [1024,64] -> g_qkv scratch [B,H,N,D]
    sgemm<128,64,8,8,4><<<dim3(1, SEQ/128, BH), 256>>>(
        SEQ, attn_dst, SEQ, (long long)SEQ*SEQ,
        v, HD, (long long)SEQ*HD,
        qkv, HD, (long long)SEQ*HD,
        1.0f, nullptr);

    // 6. [B,H,N,D] -> [B,N,C]
    reorder_heads<<<(unsigned)((OUTE + 255)/256), 256>>>(qkv);

    // 7. out = heads @ w_proj + b_proj
    sgemm<128,128,8,8,8><<<dim3(CH/128, (BATCH*SEQ)/128, 1), 256>>>(
        CH, heads, CH, 0, w_proj, CH, 0, out, CH, 0, 1.0f, b_proj);
}

// round 5
// speedup vs baseline: 1.2479x; 1.2479x over previous
#include <cuda_runtime.h>
#include <cuda_bf16.h>
#include <cstdint>
#include <math.h>

#define BATCH 8
#define SEQ   1024
#define CH    768
#define NH    12
#define HD    64
#define BH    (BATCH*NH)   /* 96 */

// ===================== scratch (__device__ globals) =======================
__device__ float g_qkv   [(size_t)BATCH*SEQ*3*CH];   // fp32 qkv; reused as AV output
__device__ float g_scores[(size_t)BH*SEQ*SEQ];       // fp32 scores (attn fallback)

#define BF16_BUF(name, elems) __device__ uint4 name[(size_t)(elems)/8]
BF16_BUF(g_xh, 6291456);       BF16_BUF(g_xl, 6291456);        // x split [8192,768]
BF16_BUF(g_wqkvTh, 1769472);   BF16_BUF(g_wqkvTl, 1769472);    // w_qkv^T [2304,768]
BF16_BUF(g_wprojTh, 589824);   BF16_BUF(g_wprojTl, 589824);    // w_proj^T [768,768]
BF16_BUF(g_qh, 6291456);       BF16_BUF(g_ql, 6291456);        // q [BH,1024,64]
BF16_BUF(g_kh, 6291456);       BF16_BUF(g_kl, 6291456);        // k [BH,1024,64]
BF16_BUF(g_vTh, 6291456);      BF16_BUF(g_vTl, 6291456);       // v^T [BH,64,1024]
BF16_BUF(g_ah, 100663296);     BF16_BUF(g_al, 100663296);      // attn split [BH,1024,1024]
BF16_BUF(g_hh, 6291456);       BF16_BUF(g_hl, 6291456);        // heads split [8192,768]

// ===================== PTX helpers (sm_80-portable only) ==================
__device__ __forceinline__ uint32_t smem_u32(const void* p){
    uint32_t a;
    asm("{ .reg .u64 t; cvta.to.shared.u64 t, %1; cvt.u32.u64 %0, t; }" : "=r"(a) : "l"(p));
    return a;
}
__device__ __forceinline__ void cp16(uint32_t dst, const void* src){
    asm volatile("cp.async.cg.shared.global [%0], [%1], 16;" :: "r"(dst), "l"(src));
}
#define CP_COMMIT() asm volatile("cp.async.commit_group;" ::: "memory")
#define CP_WAIT(n)  asm volatile("cp.async.wait_group %0;" :: "n"(n) : "memory")

#define LDSM4(r0,r1,r2,r3,a) \
    asm volatile("ldmatrix.sync.aligned.m8n8.x4.shared.b16 {%0,%1,%2,%3}, [%4];" \
        : "=r"(r0),"=r"(r1),"=r"(r2),"=r"(r3) : "r"(a))

#define MMA16816(c, a, b0, b1) \
    asm volatile("mma.sync.aligned.m16n8k16.row.col.f32.bf16.bf16.f32 " \
        "{%0,%1,%2,%3},{%4,%5,%6,%7},{%8,%9},{%0,%1,%2,%3};" \
        : "+f"((c)[0]),"+f"((c)[1]),"+f"((c)[2]),"+f"((c)[3]) \
        : "r"((a)[0]),"r"((a)[1]),"r"((a)[2]),"r"((a)[3]), "r"(b0),"r"(b1))

// ===================== mma.sync bf16 split GEMM ===========================
// C[M,N] = alpha*(Ah+Al)[M,K] @ ((Bh+Bl)[N,K])^T (+bias).
// 3-term split fused in the inner loop. BM=128, BK=32, 256 threads (8 warps).
template<int BN, int WROWS, int WCOLS>
__global__ void __launch_bounds__(256, 1) gemm_mma(
    int K,
    const __nv_bfloat16* __restrict__ Ah, const __nv_bfloat16* __restrict__ Al, int lda, long long sA,
    const __nv_bfloat16* __restrict__ Bh, const __nv_bfloat16* __restrict__ Bl, int ldb, long long sB,
    float* __restrict__ C, int ldc, long long sC,
    float alpha, const float* __restrict__ bias)
{
    constexpr int BM = 128, BK = 32, STRIDE = BK + 8;   // 80B rows: conflict-free ldmatrix
    constexpr int WM = BM / WROWS, WN = BN / WCOLS;
    constexpr int MI = WM / 16, NI = WN / 8;
    constexpr int ATILE = BM * STRIDE;                  // elems
    constexpr int BTILE = BN * STRIDE;
    constexpr int STAGE = 2*ATILE + 2*BTILE;

    extern __shared__ char sm[];
    const uint32_t sb = smem_u32(sm);

    const int tid = threadIdx.x;
    const int lane = tid & 31, wid = tid >> 5;
    const int wr = wid / WCOLS, wc = wid % WCOLS;
    const int lrow = lane & 15, lhalf = (lane >> 4) * 8;

    const long long bz = blockIdx.z;
    const __nv_bfloat16* Aht = Ah + bz*sA + (long long)blockIdx.y*BM*lda;
    const __nv_bfloat16* Alt = Al + bz*sA + (long long)blockIdx.y*BM*lda;
    const __nv_bfloat16* Bht = Bh + bz*sB + (long long)blockIdx.x*BN*ldb;
    const __nv_bfloat16* Blt = Bl + bz*sB + (long long)blockIdx.x*BN*ldb;
    C += bz*sC + (long long)blockIdx.y*BM*ldc + (long long)blockIdx.x*BN;

    float acc[MI][NI][4];
    #pragma unroll
    for (int mi=0;mi<MI;mi++)
        #pragma unroll
        for (int ni=0;ni<NI;ni++)
            #pragma unroll
            for (int r=0;r<4;r++) acc[mi][ni][r]=0.f;

    const int NC = K >> 5;

    auto load_stage = [&](int chunk, int s){
        const int k0 = chunk << 5;
        const uint32_t base = sb + (uint32_t)(s*STAGE)*2;
        #pragma unroll
        for (int j=0;j<2;j++){
            int id = tid + j*256, row = id >> 2, kc = id & 3;
            uint32_t d = base + (uint32_t)(row*STRIDE + kc*8)*2;
            const __nv_bfloat16* g = Aht + (size_t)row*lda + k0 + kc*8;
            cp16(d, g);
            cp16(d + ATILE*2, Alt + (size_t)row*lda + k0 + kc*8);
        }
        #pragma unroll
        for (int j=0;j<BN/64;j++){
            int id = tid + j*256, row = id >> 2, kc = id & 3;
            uint32_t d = base + (uint32_t)(2*ATILE + row*STRIDE + kc*8)*2;
            cp16(d, Bht + (size_t)row*ldb + k0 + kc*8);
            cp16(d + BTILE*2, Blt + (size_t)row*ldb + k0 + kc*8);
        }
    };

    auto compute_stage = [&](int s){
        const uint32_t base = sb + (uint32_t)(s*STAGE)*2;
        #pragma unroll
        for (int k16=0;k16<2;k16++){
            uint32_t ah[MI][4], al[MI][4];
            #pragma unroll
            for (int mi=0;mi<MI;mi++){
                uint32_t a = base + (uint32_t)((wr*WM + mi*16 + lrow)*STRIDE + k16*16 + lhalf)*2;
                LDSM4(ah[mi][0],ah[mi][1],ah[mi][2],ah[mi][3], a);
                LDSM4(al[mi][0],al[mi][1],al[mi][2],al[mi][3], a + ATILE*2);
            }
            uint32_t bh[NI][2], bl[NI][2];
            #pragma unroll
            for (int p=0;p<NI/2;p++){
                uint32_t a = base + (uint32_t)(2*ATILE + (wc*WN + p*16 + lrow)*STRIDE + k16*16 + lhalf)*2;
                uint32_t r0,r1,r2,r3;
                LDSM4(r0,r1,r2,r3, a);
                bh[2*p][0]=r0; bh[2*p][1]=r2; bh[2*p+1][0]=r1; bh[2*p+1][1]=r3;
                LDSM4(r0,r1,r2,r3, a + BTILE*2);
                bl[2*p][0]=r0; bl[2*p][1]=r2; bl[2*p+1][0]=r1; bl[2*p+1][1]=r3;
            }
            #pragma unroll
            for (int mi=0;mi<MI;mi++)
                #pragma unroll
                for (int ni=0;ni<NI;ni++){
                    MMA16816(acc[mi][ni], ah[mi], bh[ni][0], bh[ni][1]);
                    MMA16816(acc[mi][ni], ah[mi], bl[ni][0], bl[ni][1]);
                    MMA16816(acc[mi][ni], al[mi], bh[ni][0], bh[ni][1]);
                }
        }
    };

    load_stage(0, 0);
    CP_COMMIT();
    int buf = 0;
    for (int i=0;i<NC;i++){
        if (i+1 < NC){
            load_stage(i+1, buf^1);
            CP_COMMIT();
            CP_WAIT(1);
        } else {
            CP_WAIT(0);
        }
        __syncthreads();
        compute_stage(buf);
        __syncthreads();
        buf ^= 1;
    }

    // epilogue
    const float* bp = bias ? (bias + (long long)blockIdx.x*BN) : nullptr;
    #pragma unroll
    for (int mi=0;mi<MI;mi++){
        #pragma unroll
        for (int ni=0;ni<NI;ni++){
            int row = wr*WM + mi*16 + (lane >> 2);
            int col = wc*WN + ni*8 + (lane & 3)*2;
            float2 v0, v1;
            v0.x = alpha*acc[mi][ni][0];
            v0.y = alpha*acc[mi][ni][1];
            v1.x = alpha*acc[mi][ni][2];
            v1.y = alpha*acc[mi][ni][3];
            if (bp){
                float b0 = bp[col], b1 = bp[col+1];
                v0.x += b0; v0.y += b1; v1.x += b0; v1.y += b1;
            }
            *(float2*)(C + (long long)row*ldc + col) = v0;
            *(float2*)(C + (long long)(row+8)*ldc + col) = v1;
        }
    }
}

// ===================== split / transpose / reorder ========================
__device__ __forceinline__ void split1(float v, __nv_bfloat16& h, __nv_bfloat16& l){
    h = __float2bfloat16(v);
    l = __float2bfloat16(v - __bfloat162float(h));
}

__global__ void split_fp32(const float* __restrict__ src,
                           __nv_bfloat16* __restrict__ hi, __nv_bfloat16* __restrict__ lo,
                           long long n)
{
    long long i = ((long long)blockIdx.x*blockDim.x + threadIdx.x) * 4;
    if (i >= n) return;
    float4 v = *(const float4*)(src + i);
    __nv_bfloat16 h, l;
    split1(v.x, h, l); hi[i+0]=h; lo[i+0]=l;
    split1(v.y, h, l); hi[i+1]=h; lo[i+1]=l;
    split1(v.z, h, l); hi[i+2]=h; lo[i+2]=l;
    split1(v.w, h, l); hi[i+3]=h; lo[i+3]=l;
}

// src [R,C] fp32 -> hiT/loT [C,R] bf16
__global__ void transpose_split(const float* __restrict__ src, int R, int C,
                                __nv_bfloat16* __restrict__ hiT, __nv_bfloat16* __restrict__ loT)
{
    __shared__ float t[32][33];
    int c0 = blockIdx.x*32, r0 = blockIdx.y*32;
    int x = threadIdx.x, y = threadIdx.y;
    #pragma unroll
    for (int j = 0; j < 32; j += 8)
        t[y+j][x] = src[(long long)(r0+y+j)*C + c0 + x];
    __syncthreads();
    #pragma unroll
    for (int j = 0; j < 32; j += 8){
        float v = t[x][y+j];
        long long o = (long long)(c0+y+j)*R + r0 + x;
        __nv_bfloat16 h, l; split1(v, h, l);
        hiT[o] = h; loT[o] = l;
    }
}

// g_qkv fp32 [B,N,3C] -> q_hi/lo [BH,N,64], k_hi/lo [BH,N,64], vT_hi/lo [BH,64,N]
__global__ void reorder_qkv_split(__nv_bfloat16* __restrict__ qh, __nv_bfloat16* __restrict__ ql,
                                  __nv_bfloat16* __restrict__ kh, __nv_bfloat16* __restrict__ kl,
                                  __nv_bfloat16* __restrict__ vh, __nv_bfloat16* __restrict__ vl)
{
    long long idx = (long long)blockIdx.x*blockDim.x + threadIdx.x;
    const long long total = (long long)BATCH*SEQ*3*CH;
    if (idx >= total) return;
    int c = (int)(idx % (3*CH));
    long long r = idx / (3*CH);
    int n = (int)(r % SEQ);
    int b = (int)(r / SEQ);
    int which = c / CH;
    int hc = c % CH;
    int h = hc / HD, d = hc % HD;
    long long bh = (long long)b*NH + h;
    __nv_bfloat16 bh16, bl16;
    split1(g_qkv[idx], bh16, bl16);
    if (which == 0){ long long o = (bh*SEQ + n)*HD + d; qh[o]=bh16; ql[o]=bl16; }
    else if (which == 1){ long long o = (bh*SEQ + n)*HD + d; kh[o]=bh16; kl[o]=bl16; }
    else { long long o = (bh*HD + d)*SEQ + n; vh[o]=bh16; vl[o]=bl16; }
}

// av fp32 [B,H,N,D] (in g_qkv) -> heads_hi/lo [B,N,C] bf16
__global__ void reorder_heads_split(const float* __restrict__ src,
                                    __nv_bfloat16* __restrict__ hh, __nv_bfloat16* __restrict__ hl)
{
    long long idx = (long long)blockIdx.x*blockDim.x + threadIdx.x;
    const long long total = (long long)BATCH*SEQ*CH;
    if (idx >= total) return;
    int c = (int)(idx % CH);
    long long r = idx / CH;
    int n = (int)(r % SEQ);
    int b = (int)(r / SEQ);
    int h = c / HD, d = c % HD;
    __nv_bfloat16 bh16, bl16;
    split1(src[(((long long)b*NH + h)*SEQ + n)*HD + d], bh16, bl16);
    hh[idx] = bh16; hl[idx] = bl16;
}

// ===================== softmax (fused fp32 + bf16-split output) ===========
__inline__ __device__ float warpMax(float v){
    #pragma unroll
    for (int o=16;o;o>>=1) v = fmaxf(v, __shfl_xor_sync(0xffffffffu, v, o));
    return v;
}
__inline__ __device__ float warpSum(float v){
    #pragma unroll
    for (int o=16;o;o>>=1) v += __shfl_xor_sync(0xffffffffu, v, o);
    return v;
}

__global__ void softmax_rows_split(const float* __restrict__ src, float* __restrict__ dst,
                                   __nv_bfloat16* __restrict__ dhi, __nv_bfloat16* __restrict__ dlo)
{
    long long row = blockIdx.x;
    const float* p = src + row*SEQ;
    float* o = dst + row*SEQ;
    __nv_bfloat16* oh = dhi + row*SEQ;
    __nv_bfloat16* ol = dlo + row*SEQ;
    int t = threadIdx.x;
    __shared__ float sred[8];

    float v[4];
    float m = -1e30f;
    #pragma unroll
    for (int j=0;j<4;j++){ v[j] = p[t + j*256]; m = fmaxf(m, v[j]); }
    m = warpMax(m);
    if ((t & 31) == 0) sred[t>>5] = m;
    __syncthreads();
    if (t < 32){
        float x = (t < 8) ? sred[t] : -1e30f;
        x = warpMax(x);
        if (t == 0) sred[0] = x;
    }
    __syncthreads();
    m = sred[0];
    __syncthreads();

    float s = 0.f;
    #pragma unroll
    for (int j=0;j<4;j++){ v[j] = expf(v[j]-m); s += v[j]; }
    s = warpSum(s);
    if ((t & 31) == 0) sred[t>>5] = s;
    __syncthreads();
    if (t < 32){
        float x = (t < 8) ? sred[t] : 0.f;
        x = warpSum(x);
        if (t == 0) sred[0] = x;
    }
    __syncthreads();
    float inv = 1.0f / sred[0];
    #pragma unroll
    for (int j=0;j<4;j++){
        float a = v[j]*inv;
        o[t + j*256] = a;
        __nv_bfloat16 h, l; split1(a, h, l);
        oh[t + j*256] = h;
        ol[t + j*256] = l;
    }
}

// ===================== launch =============================================
extern "C" void kernel_launch(void* const* d_in, const int* in_sizes, int n_in,
                              void* d_out, int out_size)
{
    const float* x      = (const float*)d_in[0];   // [8,1024,768]
    const float* w_qkv  = (const float*)d_in[1];   // [768,2304]
    const float* w_proj = (const float*)d_in[2];   // [768,768]
    const float* b_proj = (const float*)d_in[3];   // [768]
    float* out = (float*)d_out;

    float *qkv, *scores;
    cudaGetSymbolAddress((void**)&qkv,    g_qkv);
    cudaGetSymbolAddress((void**)&scores, g_scores);
    void *xh,*xl,*wqh,*wql,*wph,*wpl,*qh,*ql,*kh,*kl,*vh,*vl,*ah,*al,*hh,*hl;
    cudaGetSymbolAddress(&xh, g_xh);     cudaGetSymbolAddress(&xl, g_xl);
    cudaGetSymbolAddress(&wqh, g_wqkvTh); cudaGetSymbolAddress(&wql, g_wqkvTl);
    cudaGetSymbolAddress(&wph, g_wprojTh); cudaGetSymbolAddress(&wpl, g_wprojTl);
    cudaGetSymbolAddress(&qh, g_qh);     cudaGetSymbolAddress(&ql, g_ql);
    cudaGetSymbolAddress(&kh, g_kh);     cudaGetSymbolAddress(&kl, g_kl);
    cudaGetSymbolAddress(&vh, g_vTh);    cudaGetSymbolAddress(&vl, g_vTl);
    cudaGetSymbolAddress(&ah, g_ah);     cudaGetSymbolAddress(&al, g_al);
    cudaGetSymbolAddress(&hh, g_hh);     cudaGetSymbolAddress(&hl, g_hl);
    #define BF(p) ((__nv_bfloat16*)(p))

    // dynamic smem: BN=128 -> 81920B, BN=64 -> 61440B
    cudaFuncSetAttribute(gemm_mma<128,2,4>, cudaFuncAttributeMaxDynamicSharedMemorySize, 81920);
    cudaFuncSetAttribute(gemm_mma<64,4,2>,  cudaFuncAttributeMaxDynamicSharedMemorySize, 61440);

    const long long OUTE  = (long long)BATCH*SEQ*CH;
    const long long ATTNE = (long long)BH*SEQ*SEQ;
    float* attn_dst = ((long long)out_size >= OUTE + ATTNE) ? (out + OUTE) : scores;

    // 1. split x; transpose+split weights
    split_fp32<<<(unsigned)((OUTE/4 + 255)/256), 256>>>(x, BF(xh), BF(xl), OUTE);
    transpose_split<<<dim3(3*CH/32, CH/32), dim3(32,8)>>>(w_qkv, CH, 3*CH, BF(wqh), BF(wql));
    transpose_split<<<dim3(CH/32, CH/32),   dim3(32,8)>>>(w_proj, CH, CH,  BF(wph), BF(wpl));

    // 2. qkv = x @ w_qkv   [8192,768]x[768,2304]
    gemm_mma<128,2,4><<<dim3(3*CH/128, (BATCH*SEQ)/128, 1), 256, 81920>>>(
        CH, BF(xh), BF(xl), CH, 0,
        BF(wqh), BF(wql), CH, 0,
        qkv, 3*CH, 0, 1.0f, nullptr);

    // 3. split into q / k / v^T (bf16 hi/lo)
    {
        long long total = (long long)BATCH*SEQ*3*CH;
        reorder_qkv_split<<<(unsigned)((total + 255)/256), 256>>>(
            BF(qh), BF(ql), BF(kh), BF(kl), BF(vh), BF(vl));
    }

    // 4. scores = (1/8) q @ k^T   batched [1024,64]x[64,1024]
    gemm_mma<128,2,4><<<dim3(SEQ/128, SEQ/128, BH), 256, 81920>>>(
        HD, BF(qh), BF(ql), HD, (long long)SEQ*HD,
        BF(kh), BF(kl), HD, (long long)SEQ*HD,
        scores, SEQ, (long long)SEQ*SEQ, 0.125f, nullptr);

    // 5. softmax + bf16 split (fused)
    softmax_rows_split<<<BH*SEQ, 256>>>(scores, attn_dst, BF(ah), BF(al));

    // 6. av = attn @ v   batched [1024,1024]x[1024,64] -> g_qkv scratch [BH,1024,64]
    gemm_mma<64,4,2><<<dim3(1, SEQ/128, BH), 256, 61440>>>(
        SEQ, BF(ah), BF(al), SEQ, (long long)SEQ*SEQ,
        BF(vh), BF(vl), SEQ, (long long)HD*SEQ,
        qkv, HD, (long long)SEQ*HD, 1.0f, nullptr);

    // 7. [B,H,N,D] -> heads bf16 split [B,N,C]
    reorder_heads_split<<<(unsigned)((OUTE + 255)/256), 256>>>(qkv, BF(hh), BF(hl));

    // 8. out = heads @ w_proj + b_proj
    gemm_mma<128,2,4><<<dim3(CH/128, (BATCH*SEQ)/128, 1), 256, 81920>>>(
        CH, BF(hh), BF(hl), CH, 0,
        BF(wph), BF(wpl), CH, 0,
        out, CH, 0, 1.0f, b_proj);
}

// round 6
// speedup vs baseline: 1.8236x; 1.4613x over previous
#include <cuda_runtime.h>
#include <cuda_fp16.h>
#include <cstdint>
#include <math.h>

#define BATCH 8
#define SEQ   1024
#define CH    768
#define NH    12
#define HD    64
#define BH    (BATCH*NH)   /* 96 */

// ===================== scratch (__device__ globals) =======================
__device__ float g_qkv   [(size_t)BATCH*SEQ*3*CH];   // fp32 qkv; reused as AV output
__device__ float g_scores[(size_t)BH*SEQ*SEQ];       // fp32 scores (attn fallback)

#define H16_BUF(name, elems) __device__ uint4 name[(size_t)(elems)/8]
H16_BUF(g_xh, 6291456);       H16_BUF(g_xl, 6291456);        // x split [8192,768]
H16_BUF(g_wqkvTh, 1769472);   H16_BUF(g_wqkvTl, 1769472);    // w_qkv^T [2304,768]
H16_BUF(g_wprojTh, 589824);   H16_BUF(g_wprojTl, 589824);    // w_proj^T [768,768]
H16_BUF(g_qh, 6291456);       H16_BUF(g_ql, 6291456);        // q [BH,1024,64]
H16_BUF(g_kh, 6291456);       H16_BUF(g_kl, 6291456);        // k [BH,1024,64]
H16_BUF(g_vTh, 6291456);      H16_BUF(g_vTl, 6291456);       // v^T [BH,64,1024]
H16_BUF(g_ah, 100663296);     H16_BUF(g_al, 100663296);      // attn split [BH,1024,1024]
H16_BUF(g_hh, 6291456);       H16_BUF(g_hl, 6291456);        // heads split [8192,768]

// ===================== PTX helpers (sm_80-portable only) ==================
__device__ __forceinline__ uint32_t smem_u32(const void* p){
    uint32_t a;
    asm("{ .reg .u64 t; cvta.to.shared.u64 t, %1; cvt.u32.u64 %0, t; }" : "=r"(a) : "l"(p));
    return a;
}
__device__ __forceinline__ void cp16(uint32_t dst, const void* src){
    asm volatile("cp.async.cg.shared.global [%0], [%1], 16;" :: "r"(dst), "l"(src));
}
#define CP_COMMIT() asm volatile("cp.async.commit_group;" ::: "memory")
#define CP_WAIT(n)  asm volatile("cp.async.wait_group %0;" :: "n"(n) : "memory")

#define LDSM4(r0,r1,r2,r3,a) \
    asm volatile("ldmatrix.sync.aligned.m8n8.x4.shared.b16 {%0,%1,%2,%3}, [%4];" \
        : "=r"(r0),"=r"(r1),"=r"(r2),"=r"(r3) : "r"(a))

#define MMA16816(c, a, b0, b1) \
    asm volatile("mma.sync.aligned.m16n8k16.row.col.f32.f16.f16.f32 " \
        "{%0,%1,%2,%3},{%4,%5,%6,%7},{%8,%9},{%0,%1,%2,%3};" \
        : "+f"((c)[0]),"+f"((c)[1]),"+f"((c)[2]),"+f"((c)[3]) \
        : "r"((a)[0]),"r"((a)[1]),"r"((a)[2]),"r"((a)[3]), "r"(b0),"r"(b1))

// ===================== mma.sync fp16 split GEMM (4-stage) =================
// C[M,N] = alpha*(Ah+Al)[M,K] @ ((Bh+Bl)[N,K])^T (+bias); 3-term split.
// BM=128, BK=32, 256 threads (8 warps), 4-stage cp.async, 1 sync per iter.
template<int BN, int WROWS, int WCOLS>
__global__ void __launch_bounds__(256, 1) gemm_mma(
    int K,
    const __half* __restrict__ Ah, const __half* __restrict__ Al, int lda, long long sA,
    const __half* __restrict__ Bh, const __half* __restrict__ Bl, int ldb, long long sB,
    float* __restrict__ C, int ldc, long long sC,
    float alpha, const float* __restrict__ bias)
{
    constexpr int BM = 128, BK = 32, STRIDE = BK + 8, S = 4;
    constexpr int WM = BM / WROWS, WN = BN / WCOLS;
    constexpr int MI = WM / 16, NI = WN / 8;
    constexpr int ATILE = BM * STRIDE;                  // elems
    constexpr int BTILE = BN * STRIDE;
    constexpr int STAGE = 2*ATILE + 2*BTILE;

    extern __shared__ char sm[];
    const uint32_t sb = smem_u32(sm);

    const int tid = threadIdx.x;
    const int lane = tid & 31, wid = tid >> 5;
    const int wr = wid / WCOLS, wc = wid % WCOLS;
    const int lrow = lane & 15, lhalf = (lane >> 4) * 8;

    const long long bz = blockIdx.z;
    const __half* Aht = Ah + bz*sA + (long long)blockIdx.y*BM*lda;
    const __half* Alt = Al + bz*sA + (long long)blockIdx.y*BM*lda;
    const __half* Bht = Bh + bz*sB + (long long)blockIdx.x*BN*ldb;
    const __half* Blt = Bl + bz*sB + (long long)blockIdx.x*BN*ldb;
    C += bz*sC + (long long)blockIdx.y*BM*ldc + (long long)blockIdx.x*BN;

    float acc[MI][NI][4];
    #pragma unroll
    for (int mi=0;mi<MI;mi++)
        #pragma unroll
        for (int ni=0;ni<NI;ni++)
            #pragma unroll
            for (int r=0;r<4;r++) acc[mi][ni][r]=0.f;

    const int NC = K >> 5;

    // loads one BK chunk into stage s (guarded), always commits one group
    auto load_stage = [&](int chunk, int s){
        if (chunk < NC){
            const int k0 = chunk << 5;
            const uint32_t base = sb + (uint32_t)(s*STAGE)*2;
            #pragma unroll
            for (int j=0;j<2;j++){
                int id = tid + j*256, row = id >> 2, kc = id & 3;
                uint32_t d = base + (uint32_t)(row*STRIDE + kc*8)*2;
                const size_t go = (size_t)row*lda + k0 + kc*8;
                cp16(d, Aht + go);
                cp16(d + ATILE*2, Alt + go);
            }
            #pragma unroll
            for (int j=0;j<BN/64;j++){
                int id = tid + j*256, row = id >> 2, kc = id & 3;
                uint32_t d = base + (uint32_t)(2*ATILE + row*STRIDE + kc*8)*2;
                const size_t go = (size_t)row*ldb + k0 + kc*8;
                cp16(d, Bht + go);
                cp16(d + BTILE*2, Blt + go);
            }
        }
        CP_COMMIT();
    };

    auto compute_stage = [&](int s){
        const uint32_t base = sb + (uint32_t)(s*STAGE)*2;
        #pragma unroll
        for (int k16=0;k16<2;k16++){
            uint32_t ah[MI][4], al[MI][4];
            #pragma unroll
            for (int mi=0;mi<MI;mi++){
                uint32_t a = base + (uint32_t)((wr*WM + mi*16 + lrow)*STRIDE + k16*16 + lhalf)*2;
                LDSM4(ah[mi][0],ah[mi][1],ah[mi][2],ah[mi][3], a);
                LDSM4(al[mi][0],al[mi][1],al[mi][2],al[mi][3], a + ATILE*2);
            }
            uint32_t bh[NI][2], bl[NI][2];
            #pragma unroll
            for (int p=0;p<NI/2;p++){
                uint32_t a = base + (uint32_t)(2*ATILE + (wc*WN + p*16 + lrow)*STRIDE + k16*16 + lhalf)*2;
                uint32_t r0,r1,r2,r3;
                LDSM4(r0,r1,r2,r3, a);
                bh[2*p][0]=r0; bh[2*p][1]=r2; bh[2*p+1][0]=r1; bh[2*p+1][1]=r3;
                LDSM4(r0,r1,r2,r3, a + BTILE*2);
                bl[2*p][0]=r0; bl[2*p][1]=r2; bl[2*p+1][0]=r1; bl[2*p+1][1]=r3;
            }
            #pragma unroll
            for (int mi=0;mi<MI;mi++)
                #pragma unroll
                for (int ni=0;ni<NI;ni++){
                    MMA16816(acc[mi][ni], ah[mi], bh[ni][0], bh[ni][1]);
                    MMA16816(acc[mi][ni], ah[mi], bl[ni][0], bl[ni][1]);
                    MMA16816(acc[mi][ni], al[mi], bh[ni][0], bh[ni][1]);
                }
        }
    };

    // prologue: stages 0..S-2
    #pragma unroll
    for (int s=0;s<S-1;s++) load_stage(s, s);

    int buf = 0;
    for (int i=0;i<NC;i++){
        CP_WAIT(S-2);            // chunk i resident
        __syncthreads();         // all warps done with buffer (i-1)%S
        compute_stage(buf);
        load_stage(i + S - 1, (i + S - 1) & (S-1));  // refill freed buffer
        buf = (buf + 1) & (S-1);
    }

    // epilogue
    const float* bp = bias ? (bias + (long long)blockIdx.x*BN) : nullptr;
    #pragma unroll
    for (int mi=0;mi<MI;mi++){
        #pragma unroll
        for (int ni=0;ni<NI;ni++){
            int row = wr*WM + mi*16 + (lane >> 2);
            int col = wc*WN + ni*8 + (lane & 3)*2;
            float2 v0, v1;
            v0.x = alpha*acc[mi][ni][0];
            v0.y = alpha*acc[mi][ni][1];
            v1.x = alpha*acc[mi][ni][2];
            v1.y = alpha*acc[mi][ni][3];
            if (bp){
                float b0 = bp[col], b1 = bp[col+1];
                v0.x += b0; v0.y += b1; v1.x += b0; v1.y += b1;
            }
            *(float2*)(C + (long long)row*ldc + col) = v0;
            *(float2*)(C + (long long)(row+8)*ldc + col) = v1;
        }
    }
}

// ===================== split / transpose / reorder ========================
__device__ __forceinline__ void split1(float v, __half& h, __half& l){
    h = __float2half_rn(v);
    l = __float2half_rn(v - __half2float(h));
}

__global__ void split_fp32(const float* __restrict__ src,
                           __half* __restrict__ hi, __half* __restrict__ lo,
                           long long n)
{
    long long i = ((long long)blockIdx.x*blockDim.x + threadIdx.x) * 4;
    if (i >= n) return;
    float4 v = *(const float4*)(src + i);
    __half h, l;
    split1(v.x, h, l); hi[i+0]=h; lo[i+0]=l;
    split1(v.y, h, l); hi[i+1]=h; lo[i+1]=l;
    split1(v.z, h, l); hi[i+2]=h; lo[i+2]=l;
    split1(v.w, h, l); hi[i+3]=h; lo[i+3]=l;
}

// src [R,C] fp32 -> hiT/loT [C,R] half
__global__ void transpose_split(const float* __restrict__ src, int R, int C,
                                __half* __restrict__ hiT, __half* __restrict__ loT)
{
    __shared__ float t[32][33];
    int c0 = blockIdx.x*32, r0 = blockIdx.y*32;
    int x = threadIdx.x, y = threadIdx.y;
    #pragma unroll
    for (int j = 0; j < 32; j += 8)
        t[y+j][x] = src[(long long)(r0+y+j)*C + c0 + x];
    __syncthreads();
    #pragma unroll
    for (int j = 0; j < 32; j += 8){
        float v = t[x][y+j];
        long long o = (long long)(c0+y+j)*R + r0 + x;
        __half h, l; split1(v, h, l);
        hiT[o] = h; loT[o] = l;
    }
}

// g_qkv fp32 [B,N,3C] -> q_hi/lo [BH,N,64], k_hi/lo [BH,N,64], vT_hi/lo [BH,64,N]
__global__ void reorder_qkv_split(__half* __restrict__ qh, __half* __restrict__ ql,
                                  __half* __restrict__ kh, __half* __restrict__ kl,
                                  __half* __restrict__ vh, __half* __restrict__ vl)
{
    long long idx = (long long)blockIdx.x*blockDim.x + threadIdx.x;
    const long long total = (long long)BATCH*SEQ*3*CH;
    if (idx >= total) return;
    int c = (int)(idx % (3*CH));
    long long r = idx / (3*CH);
    int n = (int)(r % SEQ);
    int b = (int)(r / SEQ);
    int which = c / CH;
    int hc = c % CH;
    int h = hc / HD, d = hc % HD;
    long long bh = (long long)b*NH + h;
    __half h16, l16;
    split1(g_qkv[idx], h16, l16);
    if (which == 0){ long long o = (bh*SEQ + n)*HD + d; qh[o]=h16; ql[o]=l16; }
    else if (which == 1){ long long o = (bh*SEQ + n)*HD + d; kh[o]=h16; kl[o]=l16; }
    else { long long o = (bh*HD + d)*SEQ + n; vh[o]=h16; vl[o]=l16; }
}

// av fp32 [B,H,N,D] (in g_qkv) -> heads_hi/lo [B,N,C]
__global__ void reorder_heads_split(const float* __restrict__ src,
                                    __half* __restrict__ hh, __half* __restrict__ hl)
{
    long long idx = (long long)blockIdx.x*blockDim.x + threadIdx.x;
    const long long total = (long long)BATCH*SEQ*CH;
    if (idx >= total) return;
    int c = (int)(idx % CH);
    long long r = idx / CH;
    int n = (int)(r % SEQ);
    int b = (int)(r / SEQ);
    int h = c / HD, d = c % HD;
    __half h16, l16;
    split1(src[(((long long)b*NH + h)*SEQ + n)*HD + d], h16, l16);
    hh[idx] = h16; hl[idx] = l16;
}

// ===================== softmax (fused fp32 + half-split output) ===========
__inline__ __device__ float warpMax(float v){
    #pragma unroll
    for (int o=16;o;o>>=1) v = fmaxf(v, __shfl_xor_sync(0xffffffffu, v, o));
    return v;
}
__inline__ __device__ float warpSum(float v){
    #pragma unroll
    for (int o=16;o;o>>=1) v += __shfl_xor_sync(0xffffffffu, v, o);
    return v;
}

__global__ void softmax_rows_split(const float* __restrict__ src, float* __restrict__ dst,
                                   __half* __restrict__ dhi, __half* __restrict__ dlo)
{
    long long row = blockIdx.x;
    const float* p = src + row*SEQ;
    float* o = dst + row*SEQ;
    __half* oh = dhi + row*SEQ;
    __half* ol = dlo + row*SEQ;
    int t = threadIdx.x;
    __shared__ float sred[8];

    float v[4];
    float m = -1e30f;
    #pragma unroll
    for (int j=0;j<4;j++){ v[j] = p[t + j*256]; m = fmaxf(m, v[j]); }
    m = warpMax(m);
    if ((t & 31) == 0) sred[t>>5] = m;
    __syncthreads();
    if (t < 32){
        float x = (t < 8) ? sred[t] : -1e30f;
        x = warpMax(x);
        if (t == 0) sred[0] = x;
    }
    __syncthreads();
    m = sred[0];
    __syncthreads();

    float s = 0.f;
    #pragma unroll
    for (int j=0;j<4;j++){ v[j] = expf(v[j]-m); s += v[j]; }
    s = warpSum(s);
    if ((t & 31) == 0) sred[t>>5] = s;
    __syncthreads();
    if (t < 32){
        float x = (t < 8) ? sred[t] : 0.f;
        x = warpSum(x);
        if (t == 0) sred[0] = x;
    }
    __syncthreads();
    float inv = 1.0f / sred[0];
    #pragma unroll
    for (int j=0;j<4;j++){
        float a = v[j]*inv;
        o[t + j*256] = a;
        __half h, l; split1(a, h, l);
        oh[t + j*256] = h;
        ol[t + j*256] = l;
    }
}

// ===================== launch =============================================
extern "C" void kernel_launch(void* const* d_in, const int* in_sizes, int n_in,
                              void* d_out, int out_size)
{
    const float* x      = (const float*)d_in[0];   // [8,1024,768]
    const float* w_qkv  = (const float*)d_in[1];   // [768,2304]
    const float* w_proj = (const float*)d_in[2];   // [768,768]
    const float* b_proj = (const float*)d_in[3];   // [768]
    float* out = (float*)d_out;

    float *qkv, *scores;
    cudaGetSymbolAddress((void**)&qkv,    g_qkv);
    cudaGetSymbolAddress((void**)&scores, g_scores);
    void *xh,*xl,*wqh,*wql,*wph,*wpl,*qh,*ql,*kh,*kl,*vh,*vl,*ah,*al,*hh,*hl;
    cudaGetSymbolAddress(&xh, g_xh);     cudaGetSymbolAddress(&xl, g_xl);
    cudaGetSymbolAddress(&wqh, g_wqkvTh); cudaGetSymbolAddress(&wql, g_wqkvTl);
    cudaGetSymbolAddress(&wph, g_wprojTh); cudaGetSymbolAddress(&wpl, g_wprojTl);
    cudaGetSymbolAddress(&qh, g_qh);     cudaGetSymbolAddress(&ql, g_ql);
    cudaGetSymbolAddress(&kh, g_kh);     cudaGetSymbolAddress(&kl, g_kl);
    cudaGetSymbolAddress(&vh, g_vTh);    cudaGetSymbolAddress(&vl, g_vTl);
    cudaGetSymbolAddress(&ah, g_ah);     cudaGetSymbolAddress(&al, g_al);
    cudaGetSymbolAddress(&hh, g_hh);     cudaGetSymbolAddress(&hl, g_hl);
    #define HF(p) ((__half*)(p))

    // dynamic smem: BN=128 -> 4 stages * 40960B = 163840; BN=64 -> 4*30720 = 122880
    cudaFuncSetAttribute(gemm_mma<128,2,4>, cudaFuncAttributeMaxDynamicSharedMemorySize, 163840);
    cudaFuncSetAttribute(gemm_mma<64,4,2>,  cudaFuncAttributeMaxDynamicSharedMemorySize, 122880);

    const long long OUTE  = (long long)BATCH*SEQ*CH;
    const long long ATTNE = (long long)BH*SEQ*SEQ;
    float* attn_dst = ((long long)out_size >= OUTE + ATTNE) ? (out + OUTE) : scores;

    // 1. split x; transpose+split weights
    split_fp32<<<(unsigned)((OUTE/4 + 255)/256), 256>>>(x, HF(xh), HF(xl), OUTE);
    transpose_split<<<dim3(3*CH/32, CH/32), dim3(32,8)>>>(w_qkv, CH, 3*CH, HF(wqh), HF(wql));
    transpose_split<<<dim3(CH/32, CH/32),   dim3(32,8)>>>(w_proj, CH, CH,  HF(wph), HF(wpl));

    // 2. qkv = x @ w_qkv   [8192,768]x[768,2304]
    gemm_mma<128,2,4><<<dim3(3*CH/128, (BATCH*SEQ)/128, 1), 256, 163840>>>(
        CH, HF(xh), HF(xl), CH, 0,
        HF(wqh), HF(wql), CH, 0,
        qkv, 3*CH, 0, 1.0f, nullptr);

    // 3. split into q / k / v^T (half hi/lo)
    {
        long long total = (long long)BATCH*SEQ*3*CH;
        reorder_qkv_split<<<(unsigned)((total + 255)/256), 256>>>(
            HF(qh), HF(ql), HF(kh), HF(kl), HF(vh), HF(vl));
    }

    // 4. scores = (1/8) q @ k^T   batched [1024,64]x[64,1024]
    gemm_mma<128,2,4><<<dim3(SEQ/128, SEQ/128, BH), 256, 163840>>>(
        HD, HF(qh), HF(ql), HD, (long long)SEQ*HD,
        HF(kh), HF(kl), HD, (long long)SEQ*HD,
        scores, SEQ, (long long)SEQ*SEQ, 0.125f, nullptr);

    // 5. softmax + half split (fused)
    softmax_rows_split<<<BH*SEQ, 256>>>(scores, attn_dst, HF(ah), HF(al));

    // 6. av = attn @ v   batched [1024,1024]x[1024,64] -> g_qkv scratch [BH,1024,64]
    gemm_mma<64,4,2><<<dim3(1, SEQ/128, BH), 256, 122880>>>(
        SEQ, HF(ah), HF(al), SEQ, (long long)SEQ*SEQ,
        HF(vh), HF(vl), SEQ, (long long)HD*SEQ,
        qkv, HD, (long long)SEQ*HD, 1.0f, nullptr);

    // 7. [B,H,N,D] -> heads half split [B,N,C]
    reorder_heads_split<<<(unsigned)((OUTE + 255)/256), 256>>>(qkv, HF(hh), HF(hl));

    // 8. out = heads @ w_proj + b_proj
    gemm_mma<128,2,4><<<dim3(CH/128, (BATCH*SEQ)/128, 1), 256, 163840>>>(
        CH, HF(hh), HF(hl), CH, 0,
        HF(wph), HF(wpl), CH, 0,
        out, CH, 0, 1.0f, b_proj);
}

// round 7
// speedup vs baseline: 2.0479x; 1.1230x over previous
#include <cuda_runtime.h>
#include <cuda_fp16.h>
#include <cstdint>
#include <math.h>

#define BATCH 8
#define SEQ   1024
#define CH    768
#define NH    12
#define HD    64
#define BH    (BATCH*NH)   /* 96 */

// ===================== scratch (__device__ globals) =======================
__device__ float g_qkv   [(size_t)BATCH*SEQ*3*CH];   // fp32 qkv; reused as AV output
__device__ float g_scores[(size_t)BH*SEQ*SEQ];       // fp32 scores (attn fallback)

#define H16_BUF(name, elems) __device__ uint4 name[(size_t)(elems)/8]
H16_BUF(g_xh, 6291456);       H16_BUF(g_xl, 6291456);        // x split [8192,768]
H16_BUF(g_wqkvTh, 1769472);   H16_BUF(g_wqkvTl, 1769472);    // w_qkv^T [2304,768]
H16_BUF(g_wprojTh, 589824);   H16_BUF(g_wprojTl, 589824);    // w_proj^T [768,768]
H16_BUF(g_qh, 6291456);       H16_BUF(g_ql, 6291456);        // q [BH,1024,64]
H16_BUF(g_kh, 6291456);       H16_BUF(g_kl, 6291456);        // k [BH,1024,64]
H16_BUF(g_vTh, 6291456);      H16_BUF(g_vTl, 6291456);       // v^T [BH,64,1024]
H16_BUF(g_ah, 100663296);     H16_BUF(g_al, 100663296);      // attn split [BH,1024,1024]
H16_BUF(g_hh, 6291456);       H16_BUF(g_hl, 6291456);        // heads split [8192,768]

// ===================== PTX helpers (sm_80-portable only) ==================
__device__ __forceinline__ uint32_t smem_u32(const void* p){
    uint32_t a;
    asm("{ .reg .u64 t; cvta.to.shared.u64 t, %1; cvt.u32.u64 %0, t; }" : "=r"(a) : "l"(p));
    return a;
}
__device__ __forceinline__ void cp16(uint32_t dst, const void* src){
    asm volatile("cp.async.cg.shared.global [%0], [%1], 16;" :: "r"(dst), "l"(src));
}
#define CP_COMMIT() asm volatile("cp.async.commit_group;" ::: "memory")
#define CP_WAIT(n)  asm volatile("cp.async.wait_group %0;" :: "n"(n) : "memory")

#define LDSM4(r0,r1,r2,r3,a) \
    asm volatile("ldmatrix.sync.aligned.m8n8.x4.shared.b16 {%0,%1,%2,%3}, [%4];" \
        : "=r"(r0),"=r"(r1),"=r"(r2),"=r"(r3) : "r"(a))

#define MMA16816(c, a, b0, b1) \
    asm volatile("mma.sync.aligned.m16n8k16.row.col.f32.f16.f16.f32 " \
        "{%0,%1,%2,%3},{%4,%5,%6,%7},{%8,%9},{%0,%1,%2,%3};" \
        : "+f"((c)[0]),"+f"((c)[1]),"+f"((c)[2]),"+f"((c)[3]) \
        : "r"((a)[0]),"r"((a)[1]),"r"((a)[2]),"r"((a)[3]), "r"(b0),"r"(b1))

// ===================== mma.sync fp16 split GEMM (2-stage, 2 CTA/SM) =======
// C[M,N] = alpha*(Ah+Al)[M,K] @ ((Bh+Bl)[N,K])^T (+bias); 3-term split.
// BM=128, BK=32, 256 threads (8 warps). Double-buffered: next chunk's
// cp.async issued BEFORE compute; one __syncthreads per iteration.
template<int BN, int WROWS, int WCOLS>
__global__ void __launch_bounds__(256, 2) gemm_mma(
    int K,
    const __half* __restrict__ Ah, const __half* __restrict__ Al, int lda, long long sA,
    const __half* __restrict__ Bh, const __half* __restrict__ Bl, int ldb, long long sB,
    float* __restrict__ C, int ldc, long long sC,
    float alpha, const float* __restrict__ bias)
{
    constexpr int BM = 128, BK = 32, STRIDE = BK + 8;   // 80B rows: conflict-free ldmatrix
    constexpr int WM = BM / WROWS, WN = BN / WCOLS;
    constexpr int MI = WM / 16, NI = WN / 8;
    constexpr int ATILE = BM * STRIDE;                  // elems
    constexpr int BTILE = BN * STRIDE;
    constexpr int STAGE = 2*ATILE + 2*BTILE;

    extern __shared__ char sm[];
    const uint32_t sb = smem_u32(sm);

    const int tid = threadIdx.x;
    const int lane = tid & 31, wid = tid >> 5;
    const int wr = wid / WCOLS, wc = wid % WCOLS;
    const int lrow = lane & 15, lhalf = (lane >> 4) * 8;

    const long long bz = blockIdx.z;
    const __half* Aht = Ah + bz*sA + (long long)blockIdx.y*BM*lda;
    const __half* Alt = Al + bz*sA + (long long)blockIdx.y*BM*lda;
    const __half* Bht = Bh + bz*sB + (long long)blockIdx.x*BN*ldb;
    const __half* Blt = Bl + bz*sB + (long long)blockIdx.x*BN*ldb;
    C += bz*sC + (long long)blockIdx.y*BM*ldc + (long long)blockIdx.x*BN;

    float acc[MI][NI][4];
    #pragma unroll
    for (int mi=0;mi<MI;mi++)
        #pragma unroll
        for (int ni=0;ni<NI;ni++)
            #pragma unroll
            for (int r=0;r<4;r++) acc[mi][ni][r]=0.f;

    const int NC = K >> 5;

    auto load_stage = [&](int chunk, int s){
        const int k0 = chunk << 5;
        const uint32_t base = sb + (uint32_t)(s*STAGE)*2;
        #pragma unroll
        for (int j=0;j<2;j++){
            int id = tid + j*256, row = id >> 2, kc = id & 3;
            uint32_t d = base + (uint32_t)(row*STRIDE + kc*8)*2;
            const size_t go = (size_t)row*lda + k0 + kc*8;
            cp16(d, Aht + go);
            cp16(d + ATILE*2, Alt + go);
        }
        #pragma unroll
        for (int j=0;j<BN/64;j++){
            int id = tid + j*256, row = id >> 2, kc = id & 3;
            uint32_t d = base + (uint32_t)(2*ATILE + row*STRIDE + kc*8)*2;
            const size_t go = (size_t)row*ldb + k0 + kc*8;
            cp16(d, Bht + go);
            cp16(d + BTILE*2, Blt + go);
        }
        CP_COMMIT();
    };

    auto compute_stage = [&](int s){
        const uint32_t base = sb + (uint32_t)(s*STAGE)*2;
        #pragma unroll
        for (int k16=0;k16<2;k16++){
            uint32_t ah[MI][4], al[MI][4];
            #pragma unroll
            for (int mi=0;mi<MI;mi++){
                uint32_t a = base + (uint32_t)((wr*WM + mi*16 + lrow)*STRIDE + k16*16 + lhalf)*2;
                LDSM4(ah[mi][0],ah[mi][1],ah[mi][2],ah[mi][3], a);
                LDSM4(al[mi][0],al[mi][1],al[mi][2],al[mi][3], a + ATILE*2);
            }
            uint32_t bh[NI][2], bl[NI][2];
            #pragma unroll
            for (int p=0;p<NI/2;p++){
                uint32_t a = base + (uint32_t)(2*ATILE + (wc*WN + p*16 + lrow)*STRIDE + k16*16 + lhalf)*2;
                uint32_t r0,r1,r2,r3;
                LDSM4(r0,r1,r2,r3, a);
                bh[2*p][0]=r0; bh[2*p][1]=r2; bh[2*p+1][0]=r1; bh[2*p+1][1]=r3;
                LDSM4(r0,r1,r2,r3, a + BTILE*2);
                bl[2*p][0]=r0; bl[2*p][1]=r2; bl[2*p+1][0]=r1; bl[2*p+1][1]=r3;
            }
            #pragma unroll
            for (int mi=0;mi<MI;mi++)
                #pragma unroll
                for (int ni=0;ni<NI;ni++){
                    MMA16816(acc[mi][ni], ah[mi], bh[ni][0], bh[ni][1]);
                    MMA16816(acc[mi][ni], ah[mi], bl[ni][0], bl[ni][1]);
                    MMA16816(acc[mi][ni], al[mi], bh[ni][0], bh[ni][1]);
                }
        }
    };

    load_stage(0, 0);
    for (int i=0;i<NC;i++){
        CP_WAIT(0);              // chunk i resident in buffer i&1
        __syncthreads();         // all warps done computing chunk i-1
        if (i+1 < NC) load_stage(i+1, (i+1)&1);  // overlap with compute below
        compute_stage(i&1);
    }

    // epilogue
    const float* bp = bias ? (bias + (long long)blockIdx.x*BN) : nullptr;
    #pragma unroll
    for (int mi=0;mi<MI;mi++){
        #pragma unroll
        for (int ni=0;ni<NI;ni++){
            int row = wr*WM + mi*16 + (lane >> 2);
            int col = wc*WN + ni*8 + (lane & 3)*2;
            float2 v0, v1;
            v0.x = alpha*acc[mi][ni][0];
            v0.y = alpha*acc[mi][ni][1];
            v1.x = alpha*acc[mi][ni][2];
            v1.y = alpha*acc[mi][ni][3];
            if (bp){
                float b0 = bp[col], b1 = bp[col+1];
                v0.x += b0; v0.y += b1; v1.x += b0; v1.y += b1;
            }
            *(float2*)(C + (long long)row*ldc + col) = v0;
            *(float2*)(C + (long long)(row+8)*ldc + col) = v1;
        }
    }
}

// ===================== split / transpose / reorder ========================
__device__ __forceinline__ void split1(float v, __half& h, __half& l){
    h = __float2half_rn(v);
    l = __float2half_rn(v - __half2float(h));
}

__global__ void split_fp32(const float* __restrict__ src,
                           __half* __restrict__ hi, __half* __restrict__ lo,
                           long long n)
{
    long long i = ((long long)blockIdx.x*blockDim.x + threadIdx.x) * 4;
    if (i >= n) return;
    float4 v = *(const float4*)(src + i);
    __half h, l;
    split1(v.x, h, l); hi[i+0]=h; lo[i+0]=l;
    split1(v.y, h, l); hi[i+1]=h; lo[i+1]=l;
    split1(v.z, h, l); hi[i+2]=h; lo[i+2]=l;
    split1(v.w, h, l); hi[i+3]=h; lo[i+3]=l;
}

// src [R,C] fp32 -> hiT/loT [C,R] half
__global__ void transpose_split(const float* __restrict__ src, int R, int C,
                                __half* __restrict__ hiT, __half* __restrict__ loT)
{
    __shared__ float t[32][33];
    int c0 = blockIdx.x*32, r0 = blockIdx.y*32;
    int x = threadIdx.x, y = threadIdx.y;
    #pragma unroll
    for (int j = 0; j < 32; j += 8)
        t[y+j][x] = src[(long long)(r0+y+j)*C + c0 + x];
    __syncthreads();
    #pragma unroll
    for (int j = 0; j < 32; j += 8){
        float v = t[x][y+j];
        long long o = (long long)(c0+y+j)*R + r0 + x;
        __half h, l; split1(v, h, l);
        hiT[o] = h; loT[o] = l;
    }
}

// g_qkv fp32 [B,N,3C] -> q_hi/lo [BH,N,64], k_hi/lo [BH,N,64], vT_hi/lo [BH,64,N]
__global__ void reorder_qkv_split(__half* __restrict__ qh, __half* __restrict__ ql,
                                  __half* __restrict__ kh, __half* __restrict__ kl,
                                  __half* __restrict__ vh, __half* __restrict__ vl)
{
    long long idx = (long long)blockIdx.x*blockDim.x + threadIdx.x;
    const long long total = (long long)BATCH*SEQ*3*CH;
    if (idx >= total) return;
    int c = (int)(idx % (3*CH));
    long long r = idx / (3*CH);
    int n = (int)(r % SEQ);
    int b = (int)(r / SEQ);
    int which = c / CH;
    int hc = c % CH;
    int h = hc / HD, d = hc % HD;
    long long bh = (long long)b*NH + h;
    __half h16, l16;
    split1(g_qkv[idx], h16, l16);
    if (which == 0){ long long o = (bh*SEQ + n)*HD + d; qh[o]=h16; ql[o]=l16; }
    else if (which == 1){ long long o = (bh*SEQ + n)*HD + d; kh[o]=h16; kl[o]=l16; }
    else { long long o = (bh*HD + d)*SEQ + n; vh[o]=h16; vl[o]=l16; }
}

// av fp32 [B,H,N,D] (in g_qkv) -> heads_hi/lo [B,N,C]
__global__ void reorder_heads_split(const float* __restrict__ src,
                                    __half* __restrict__ hh, __half* __restrict__ hl)
{
    long long idx = (long long)blockIdx.x*blockDim.x + threadIdx.x;
    const long long total = (long long)BATCH*SEQ*CH;
    if (idx >= total) return;
    int c = (int)(idx % CH);
    long long r = idx / CH;
    int n = (int)(r % SEQ);
    int b = (int)(r / SEQ);
    int h = c / HD, d = c % HD;
    __half h16, l16;
    split1(src[(((long long)b*NH + h)*SEQ + n)*HD + d], h16, l16);
    hh[idx] = h16; hl[idx] = l16;
}

// ===================== softmax (fused fp32 + half-split output) ===========
__inline__ __device__ float warpMax(float v){
    #pragma unroll
    for (int o=16;o;o>>=1) v = fmaxf(v, __shfl_xor_sync(0xffffffffu, v, o));
    return v;
}
__inline__ __device__ float warpSum(float v){
    #pragma unroll
    for (int o=16;o;o>>=1) v += __shfl_xor_sync(0xffffffffu, v, o);
    return v;
}

__global__ void softmax_rows_split(const float* __restrict__ src, float* __restrict__ dst,
                                   __half* __restrict__ dhi, __half* __restrict__ dlo)
{
    long long row = blockIdx.x;
    const float* p = src + row*SEQ;
    float* o = dst + row*SEQ;
    __half* oh = dhi + row*SEQ;
    __half* ol = dlo + row*SEQ;
    int t = threadIdx.x;
    __shared__ float sred[8];

    float v[4];
    float m = -1e30f;
    #pragma unroll
    for (int j=0;j<4;j++){ v[j] = p[t + j*256]; m = fmaxf(m, v[j]); }
    m = warpMax(m);
    if ((t & 31) == 0) sred[t>>5] = m;
    __syncthreads();
    if (t < 32){
        float x = (t < 8) ? sred[t] : -1e30f;
        x = warpMax(x);
        if (t == 0) sred[0] = x;
    }
    __syncthreads();
    m = sred[0];
    __syncthreads();

    float s = 0.f;
    #pragma unroll
    for (int j=0;j<4;j++){ v[j] = expf(v[j]-m); s += v[j]; }
    s = warpSum(s);
    if ((t & 31) == 0) sred[t>>5] = s;
    __syncthreads();
    if (t < 32){
        float x = (t < 8) ? sred[t] : 0.f;
        x = warpSum(x);
        if (t == 0) sred[0] = x;
    }
    __syncthreads();
    float inv = 1.0f / sred[0];
    #pragma unroll
    for (int j=0;j<4;j++){
        float a = v[j]*inv;
        o[t + j*256] = a;
        __half h, l; split1(a, h, l);
        oh[t + j*256] = h;
        ol[t + j*256] = l;
    }
}

// ===================== launch =============================================
extern "C" void kernel_launch(void* const* d_in, const int* in_sizes, int n_in,
                              void* d_out, int out_size)
{
    const float* x      = (const float*)d_in[0];   // [8,1024,768]
    const float* w_qkv  = (const float*)d_in[1];   // [768,2304]
    const float* w_proj = (const float*)d_in[2];   // [768,768]
    const float* b_proj = (const float*)d_in[3];   // [768]
    float* out = (float*)d_out;

    float *qkv, *scores;
    cudaGetSymbolAddress((void**)&qkv,    g_qkv);
    cudaGetSymbolAddress((void**)&scores, g_scores);
    void *xh,*xl,*wqh,*wql,*wph,*wpl,*qh,*ql,*kh,*kl,*vh,*vl,*ah,*al,*hh,*hl;
    cudaGetSymbolAddress(&xh, g_xh);     cudaGetSymbolAddress(&xl, g_xl);
    cudaGetSymbolAddress(&wqh, g_wqkvTh); cudaGetSymbolAddress(&wql, g_wqkvTl);
    cudaGetSymbolAddress(&wph, g_wprojTh); cudaGetSymbolAddress(&wpl, g_wprojTl);
    cudaGetSymbolAddress(&qh, g_qh);     cudaGetSymbolAddress(&ql, g_ql);
    cudaGetSymbolAddress(&kh, g_kh);     cudaGetSymbolAddress(&kl, g_kl);
    cudaGetSymbolAddress(&vh, g_vTh);    cudaGetSymbolAddress(&vl, g_vTl);
    cudaGetSymbolAddress(&ah, g_ah);     cudaGetSymbolAddress(&al, g_al);
    cudaGetSymbolAddress(&hh, g_hh);     cudaGetSymbolAddress(&hl, g_hl);
    #define HF(p) ((__half*)(p))

    // dynamic smem: 2 stages. BN=128 -> 81920B, BN=64 -> 61440B (2 CTAs/SM)
    cudaFuncSetAttribute(gemm_mma<128,2,4>, cudaFuncAttributeMaxDynamicSharedMemorySize, 81920);
    cudaFuncSetAttribute(gemm_mma<64,4,2>,  cudaFuncAttributeMaxDynamicSharedMemorySize, 61440);

    const long long OUTE  = (long long)BATCH*SEQ*CH;
    const long long ATTNE = (long long)BH*SEQ*SEQ;
    float* attn_dst = ((long long)out_size >= OUTE + ATTNE) ? (out + OUTE) : scores;

    // 1. split x; transpose+split weights
    split_fp32<<<(unsigned)((OUTE/4 + 255)/256), 256>>>(x, HF(xh), HF(xl), OUTE);
    transpose_split<<<dim3(3*CH/32, CH/32), dim3(32,8)>>>(w_qkv, CH, 3*CH, HF(wqh), HF(wql));
    transpose_split<<<dim3(CH/32, CH/32),   dim3(32,8)>>>(w_proj, CH, CH,  HF(wph), HF(wpl));

    // 2. qkv = x @ w_qkv   [8192,768]x[768,2304]
    gemm_mma<128,2,4><<<dim3(3*CH/128, (BATCH*SEQ)/128, 1), 256, 81920>>>(
        CH, HF(xh), HF(xl), CH, 0,
        HF(wqh), HF(wql), CH, 0,
        qkv, 3*CH, 0, 1.0f, nullptr);

    // 3. split into q / k / v^T (half hi/lo)
    {
        long long total = (long long)BATCH*SEQ*3*CH;
        reorder_qkv_split<<<(unsigned)((total + 255)/256), 256>>>(
            HF(qh), HF(ql), HF(kh), HF(kl), HF(vh), HF(vl));
    }

    // 4. scores = (1/8) q @ k^T   batched [1024,64]x[64,1024]
    gemm_mma<128,2,4><<<dim3(SEQ/128, SEQ/128, BH), 256, 81920>>>(
        HD, HF(qh), HF(ql), HD, (long long)SEQ*HD,
        HF(kh), HF(kl), HD, (long long)SEQ*HD,
        scores, SEQ, (long long)SEQ*SEQ, 0.125f, nullptr);

    // 5. softmax + half split (fused)
    softmax_rows_split<<<BH*SEQ, 256>>>(scores, attn_dst, HF(ah), HF(al));

    // 6. av = attn @ v   batched [1024,1024]x[1024,64] -> g_qkv scratch [BH,1024,64]
    gemm_mma<64,4,2><<<dim3(1, SEQ/128, BH), 256, 61440>>>(
        SEQ, HF(ah), HF(al), SEQ, (long long)SEQ*SEQ,
        HF(vh), HF(vl), SEQ, (long long)HD*SEQ,
        qkv, HD, (long long)SEQ*HD, 1.0f, nullptr);

    // 7. [B,H,N,D] -> heads half split [B,N,C]
    reorder_heads_split<<<(unsigned)((OUTE + 255)/256), 256>>>(qkv, HF(hh), HF(hl));

    // 8. out = heads @ w_proj + b_proj
    gemm_mma<128,2,4><<<dim3(CH/128, (BATCH*SEQ)/128, 1), 256, 81920>>>(
        CH, HF(hh), HF(hl), CH, 0,
        HF(wph), HF(wpl), CH, 0,
        out, CH, 0, 1.0f, b_proj);
}